// round 15
// baseline (speedup 1.0000x reference)
#include <cuda_runtime.h>
#include <cuda_bf16.h>
#include <math.h>
#include <stdint.h>

// PCL loss, single kernel:
//   valid = target != -1
//   p     = (target==0) ? input[i*21] : pc_input[cluster[i]]
//   loss  = sum(valid * (-w * log(max(p,1e-12)))) / max(sum(valid),1)
//
// R15: ALL bulk traffic (24KB streams/CTA + 16KB pc table) via cp.async.bulk
// (TMA path) -> bypasses the per-SM L1tex outstanding-miss-sector queue that
// capped every LDG variant at ~3.0 TB/s. Compute reads streams from smem,
// gathers pc from smem; only the sparse t==0 input-column gather uses LDG.
// 512 threads x 1024 CTAs, 40KB smem, 32 regs -> 4 CTAs/SM, full occupancy.

#define C_CLASSES 21
#define EPS 1e-12f
#define NUM_CLUSTERS 4096
#define TABLE_BYTES (NUM_CLUSTERS * 4)          // 16384
#define THREADS 512
#define NWARPS (THREADS / 32)
#define EPT 4
#define CTA_ELEMS (THREADS * EPT)               // 2048
#define STREAM_BYTES (CTA_ELEMS * 4)            // 8192 per array
#define TX_FULL (TABLE_BYTES + 3 * STREAM_BYTES)// 40960
#define LN2F 0.6931471805599453f

__device__ float        g_sum = 0.0f;
__device__ unsigned int g_cnt = 0u;
__device__ unsigned int g_done = 0u;   // wraps to 0 via atom.inc bound

__device__ __forceinline__ uint32_t smem_u32(const void* p) {
    uint32_t a;
    asm("{ .reg .u64 t; cvta.to.shared.u64 t, %1; cvt.u32.u64 %0, t; }"
        : "=r"(a) : "l"(p));
    return a;
}
__device__ __forceinline__ void bulk_g2s(uint32_t dst, const void* src,
                                         uint32_t bytes, uint32_t mb) {
    asm volatile("cp.async.bulk.shared::cta.global.mbarrier::complete_tx::bytes "
                 "[%0], [%1], %2, [%3];"
                 :: "r"(dst), "l"(src), "r"(bytes), "r"(mb) : "memory");
}
__device__ __forceinline__ void mbar_wait0(uint32_t mb) {
    asm volatile(
        "{\n\t.reg .pred P;\n"
        "W_%=:\n\t"
        "mbarrier.try_wait.parity.acquire.cta.shared::cta.b64 P, [%0], 0, 0x989680;\n\t"
        "@P bra.uni D_%=;\n\t"
        "bra.uni W_%=;\n"
        "D_%=:\n\t}" :: "r"(mb) : "memory");
}

__global__ void __launch_bounds__(THREADS)
pcl_fused(const float* __restrict__ input,
          const float* __restrict__ weight,
          const float* __restrict__ pc,
          const int* __restrict__ target,
          const int* __restrict__ cluster,
          int n, float* __restrict__ out) {
    __shared__ __align__(16) float pc_s[NUM_CLUSTERS];   // 16 KB
    __shared__ __align__(16) int   t_s[CTA_ELEMS];       //  8 KB
    __shared__ __align__(16) int   c_s[CTA_ELEMS];       //  8 KB
    __shared__ __align__(16) float w_s[CTA_ELEMS];       //  8 KB
    __shared__ __align__(8)  unsigned long long mbar;

    const int base = blockIdx.x * CTA_ELEMS;
    const bool full = (base + CTA_ELEMS <= n);

    // issue ALL bulk copies up front on one mbarrier (TMA path: no registers,
    // no L1tex miss-queue occupancy)
    if (threadIdx.x == 0) {
        uint32_t mb = smem_u32(&mbar);
        asm volatile("mbarrier.init.shared.b64 [%0], 1;" :: "r"(mb) : "memory");
        asm volatile("fence.proxy.async.shared::cta;" ::: "memory");
        uint32_t tx = full ? (uint32_t)TX_FULL : (uint32_t)TABLE_BYTES;
        asm volatile("mbarrier.arrive.expect_tx.shared.b64 _, [%0], %1;"
                     :: "r"(mb), "r"(tx) : "memory");
        bulk_g2s(smem_u32(pc_s), pc, TABLE_BYTES, mb);
        if (full) {
            bulk_g2s(smem_u32(t_s), target  + base, STREAM_BYTES, mb);
            bulk_g2s(smem_u32(c_s), cluster + base, STREAM_BYTES, mb);
            bulk_g2s(smem_u32(w_s), weight  + base, STREAM_BYTES, mb);
        }
    }
    __syncthreads();   // mbarrier init visible before any wait
    mbar_wait0(smem_u32(&mbar));

    float lsum = 0.0f;                 // accumulates w * log2(p)
    unsigned int lcnt = 0u;

    if (full) {
        const int tid = threadIdx.x;
        const int i = base + tid * EPT;

        // streams from smem (LDS.128, conflict-free)
        int4   t4 = reinterpret_cast<const int4*>(t_s)[tid];
        int4   c4 = reinterpret_cast<const int4*>(c_s)[tid];
        float4 w4 = reinterpret_cast<const float4*>(w_s)[tid];

        int   t[EPT] = {t4.x, t4.y, t4.z, t4.w};
        int   c[EPT] = {c4.x, c4.y, c4.z, c4.w};
        float w[EPT] = {w4.x, w4.y, w4.z, w4.w};

        // background LDG, branchless; inactive lanes -> input[0] (broadcast
        // sector); only ~1/21 lanes generate real traffic
        float pbg[EPT];
        #pragma unroll
        for (int k = 0; k < EPT; k++) {
            const float* a = (t[k] == 0)
                           ? input + (long long)(i + k) * C_CLASSES
                           : input;
            pbg[k] = __ldg(a);
        }
        // foreground gather from smem table (bank-conflict cost only)
        float pfg[EPT];
        #pragma unroll
        for (int k = 0; k < EPT; k++) {
            pfg[k] = pc_s[c[k] & (NUM_CLUSTERS - 1)];
        }
        // select + log2 + masked accumulate
        #pragma unroll
        for (int k = 0; k < EPT; k++) {
            float p = (t[k] == 0) ? pbg[k] : pfg[k];
            bool valid = (t[k] != -1);
            float l = __log2f(fmaxf(p, EPS));
            lsum += valid ? w[k] * l : 0.0f;
            lcnt += valid ? 1u : 0u;
        }
    } else {
        // ragged tail CTA: scalar LDG path (table already in smem)
        for (int k = base + threadIdx.x; k < n; k += THREADS) {
            int tk = target[k];
            if (tk != -1) {
                float pk = (tk == 0) ? __ldg(input + (long long)k * C_CLASSES)
                                     : pc_s[cluster[k] & (NUM_CLUSTERS - 1)];
                lsum += weight[k] * __log2f(fmaxf(pk, EPS));
                lcnt++;
            }
        }
    }

    // warp reduction
    #pragma unroll
    for (int off = 16; off > 0; off >>= 1) {
        lsum += __shfl_xor_sync(0xFFFFFFFFu, lsum, off);
        lcnt += __shfl_xor_sync(0xFFFFFFFFu, lcnt, off);
    }

    // block reduction (16 warps)
    __shared__ float        s_sum[NWARPS];
    __shared__ unsigned int s_cnt[NWARPS];
    __shared__ int          s_is_last;
    int wid = threadIdx.x >> 5;
    int lid = threadIdx.x & 31;
    if (lid == 0) { s_sum[wid] = lsum; s_cnt[wid] = lcnt; }
    __syncthreads();
    if (threadIdx.x == 0) {
        float        bs = 0.0f;
        unsigned int bc = 0u;
        #pragma unroll
        for (int w8 = 0; w8 < NWARPS; w8++) { bs += s_sum[w8]; bc += s_cnt[w8]; }
        // merge partials at the L2 coherence point (atomics bypass L1)
        atomicAdd(&g_sum, bs);
        atomicAdd(&g_cnt, bc);
        // release-only inc publishes the adds; wraps to 0 at gridDim.x-1
        // (self-reset, graph-replay deterministic); no acquire => no L1 flush
        unsigned int prev;
        asm volatile("atom.release.gpu.global.inc.u32 %0, [%1], %2;"
                     : "=r"(prev)
                     : "l"(&g_done), "r"(gridDim.x - 1)
                     : "memory");
        s_is_last = (prev == gridDim.x - 1) ? 1 : 0;
    }
    __syncthreads();

    if (s_is_last && threadIdx.x == 0) {
        // coherent reads at L2 — no acquire/L1-invalidate needed
        float        ts = atomicAdd(&g_sum, 0.0f);
        unsigned int tc = atomicAdd(&g_cnt, 0u);
        float nv = fmaxf((float)tc, 1.0f);
        *out = -(ts * LN2F) / nv;      // log2 -> ln conversion, once
        g_sum = 0.0f;                  // reset for next replay (kernel
        g_cnt = 0u;                    //  boundary orders visibility)
    }
}

extern "C" void kernel_launch(void* const* d_in, const int* in_sizes, int n_in,
                              void* d_out, int out_size) {
    const float* input   = (const float*)d_in[0];   // [N, 21]
    const float* weight  = (const float*)d_in[1];   // [N]
    const float* pc      = (const float*)d_in[2];   // [4096]
    const int*   target  = (const int*)d_in[3];     // [N] int32
    const int*   cluster = (const int*)d_in[4];     // [N] int32
    float* out = (float*)d_out;

    int n = in_sizes[1];   // weight element count == N

    int blocks = (n + CTA_ELEMS - 1) / CTA_ELEMS;  // 1024 for N=2M
    if (blocks < 1) blocks = 1;
    pcl_fused<<<blocks, THREADS>>>(input, weight, pc, target, cluster, n, out);
}

// round 16
// speedup vs baseline: 1.0363x; 1.0363x over previous
#include <cuda_runtime.h>
#include <cuda_bf16.h>
#include <math.h>
#include <stdint.h>

// PCL loss, persistent-CTA double-buffered TMA streaming kernel:
//   valid = target != -1
//   p     = (target==0) ? input[i*21] : pc_input[cluster[i]]
//   loss  = sum(valid * (-w * log(max(p,1e-12)))) / max(sum(valid),1)
//
// R16: 592 persistent CTAs (4/SM, single wave). Each CTA pipelines its tiles
// through 2 smem stages fed by cp.async.bulk: compute tile k overlaps the
// copy of tile k+1. DRAM stays continuously fed instead of burst-idle-burst
// (the structural limiter of all single-shot variants). pc table in smem
// (staged once per CTA), branchless bg gather, L2-atomic tail.

#define C_CLASSES 21
#define EPS 1e-12f
#define NUM_CLUSTERS 4096
#define THREADS 256
#define NWARPS (THREADS / 32)
#define TILE 1024
#define TILE_BYTES (TILE * 4)                  // 4096 per array
#define TILE_TX (3 * TILE_BYTES)               // 12288 per stage fill
#define GRID 592                               // 4 CTAs/SM x 148 SMs
#define LN2F 0.6931471805599453f

__device__ float        g_sum = 0.0f;
__device__ unsigned int g_cnt = 0u;
__device__ unsigned int g_done = 0u;   // wraps to 0 via atom.inc bound

__device__ __forceinline__ uint32_t smem_u32(const void* p) {
    uint32_t a;
    asm("{ .reg .u64 t; cvta.to.shared.u64 t, %1; cvt.u32.u64 %0, t; }"
        : "=r"(a) : "l"(p));
    return a;
}
__device__ __forceinline__ void bulk_g2s(uint32_t dst, const void* src,
                                         uint32_t bytes, uint32_t mb) {
    asm volatile("cp.async.bulk.shared::cta.global.mbarrier::complete_tx::bytes "
                 "[%0], [%1], %2, [%3];"
                 :: "r"(dst), "l"(src), "r"(bytes), "r"(mb) : "memory");
}
__device__ __forceinline__ void mbar_expect(uint32_t mb, uint32_t bytes) {
    asm volatile("mbarrier.arrive.expect_tx.shared.b64 _, [%0], %1;"
                 :: "r"(mb), "r"(bytes) : "memory");
}
__device__ __forceinline__ void mbar_wait(uint32_t mb, uint32_t parity) {
    asm volatile(
        "{\n\t.reg .pred P;\n"
        "W_%=:\n\t"
        "mbarrier.try_wait.parity.acquire.cta.shared::cta.b64 P, [%0], %1, 0x989680;\n\t"
        "@P bra.uni D_%=;\n\t"
        "bra.uni W_%=;\n"
        "D_%=:\n\t}" :: "r"(mb), "r"(parity) : "memory");
}

__global__ void __launch_bounds__(THREADS)
pcl_fused(const float* __restrict__ input,
          const float* __restrict__ weight,
          const float* __restrict__ pc,
          const int* __restrict__ target,
          const int* __restrict__ cluster,
          int n, float* __restrict__ out) {
    __shared__ __align__(16) float pc_s[NUM_CLUSTERS];   // 16 KB
    __shared__ __align__(16) int   t_s[2][TILE];         //  8 KB
    __shared__ __align__(16) int   c_s[2][TILE];         //  8 KB
    __shared__ __align__(16) float w_s[2][TILE];         //  8 KB
    __shared__ __align__(8)  unsigned long long mbar[2];

    const int  step  = gridDim.x;
    const int  tile0 = blockIdx.x;

    // prologue: init barriers, issue copies for this CTA's first two tiles,
    // stage the pc table via LDG (overlaps with the in-flight TMA copies)
    if (threadIdx.x == 0) {
        uint32_t mb0 = smem_u32(&mbar[0]);
        uint32_t mb1 = smem_u32(&mbar[1]);
        asm volatile("mbarrier.init.shared.b64 [%0], 1;" :: "r"(mb0) : "memory");
        asm volatile("mbarrier.init.shared.b64 [%0], 1;" :: "r"(mb1) : "memory");
        asm volatile("fence.proxy.async.shared::cta;" ::: "memory");
        #pragma unroll
        for (int pre = 0; pre < 2; pre++) {
            long tb = (long)(tile0 + pre * step) * TILE;
            if (tb + TILE <= n) {
                uint32_t mb = pre ? mb1 : mb0;
                mbar_expect(mb, TILE_TX);
                bulk_g2s(smem_u32(&t_s[pre][0]), target  + tb, TILE_BYTES, mb);
                bulk_g2s(smem_u32(&c_s[pre][0]), cluster + tb, TILE_BYTES, mb);
                bulk_g2s(smem_u32(&w_s[pre][0]), weight  + tb, TILE_BYTES, mb);
            }
        }
    }
    {   // table staging, 4 float4 per thread, overlapped with TMA
        const float4* src = reinterpret_cast<const float4*>(pc);
        #pragma unroll
        for (int k = 0; k < NUM_CLUSTERS / 4 / THREADS; k++) {
            int idx = k * THREADS + threadIdx.x;
            float4 v = __ldg(src + idx);
            *reinterpret_cast<float4*>(pc_s + idx * 4) = v;
        }
    }
    __syncthreads();   // barriers initialized + table staged

    float lsum = 0.0f;                 // accumulates w * log2(p)
    unsigned int lcnt = 0u;
    int phase[2] = {0, 0};

    int it = 0;
    for (long tile = tile0; (long)tile * TILE < n; tile += step, it++) {
        const int  s    = it & 1;
        const long base = (long)tile * TILE;
        const bool full = (base + TILE <= n);
        const uint32_t mb = smem_u32(&mbar[s]);

        if (full) {
            mbar_wait(mb, phase[s]);
            phase[s] ^= 1;

            const int tid = threadIdx.x;
            const long i = base + tid * 4;

            int4   t4 = reinterpret_cast<const int4*>(&t_s[s][0])[tid];
            int4   c4 = reinterpret_cast<const int4*>(&c_s[s][0])[tid];
            float4 w4 = reinterpret_cast<const float4*>(&w_s[s][0])[tid];

            int   t[4] = {t4.x, t4.y, t4.z, t4.w};
            int   c[4] = {c4.x, c4.y, c4.z, c4.w};
            float w[4] = {w4.x, w4.y, w4.z, w4.w};

            float pbg[4];
            #pragma unroll
            for (int k = 0; k < 4; k++) {
                const float* a = (t[k] == 0)
                               ? input + (i + k) * C_CLASSES
                               : input;             // broadcast sector
                pbg[k] = __ldg(a);
            }
            float pfg[4];
            #pragma unroll
            for (int k = 0; k < 4; k++)
                pfg[k] = pc_s[c[k] & (NUM_CLUSTERS - 1)];

            #pragma unroll
            for (int k = 0; k < 4; k++) {
                float p = (t[k] == 0) ? pbg[k] : pfg[k];
                bool valid = (t[k] != -1);
                float l = __log2f(fmaxf(p, EPS));
                lsum += valid ? w[k] * l : 0.0f;
                lcnt += valid ? 1u : 0u;
            }
        } else {
            // partial tail tile: scalar LDG path (no TMA copy was issued)
            for (long k = base + threadIdx.x; k < n; k += THREADS) {
                int tk = target[k];
                if (tk != -1) {
                    float pk = (tk == 0) ? __ldg(input + k * C_CLASSES)
                                         : pc_s[cluster[k] & (NUM_CLUSTERS - 1)];
                    lsum += weight[k] * __log2f(fmaxf(pk, EPS));
                    lcnt++;
                }
            }
        }

        __syncthreads();   // all threads done reading stage s

        // refill stage s with tile+2*step (buffer now free)
        long nt = (long)(tile + 2 * step) * TILE;
        if (threadIdx.x == 0 && nt + TILE <= n) {
            mbar_expect(mb, TILE_TX);
            bulk_g2s(smem_u32(&t_s[s][0]), target  + nt, TILE_BYTES, mb);
            bulk_g2s(smem_u32(&c_s[s][0]), cluster + nt, TILE_BYTES, mb);
            bulk_g2s(smem_u32(&w_s[s][0]), weight  + nt, TILE_BYTES, mb);
        }
    }

    // warp reduction
    #pragma unroll
    for (int off = 16; off > 0; off >>= 1) {
        lsum += __shfl_xor_sync(0xFFFFFFFFu, lsum, off);
        lcnt += __shfl_xor_sync(0xFFFFFFFFu, lcnt, off);
    }

    // block reduction (8 warps)
    __shared__ float        s_sum[NWARPS];
    __shared__ unsigned int s_cnt[NWARPS];
    __shared__ int          s_is_last;
    int wid = threadIdx.x >> 5;
    int lid = threadIdx.x & 31;
    if (lid == 0) { s_sum[wid] = lsum; s_cnt[wid] = lcnt; }
    __syncthreads();
    if (threadIdx.x == 0) {
        float        bs = 0.0f;
        unsigned int bc = 0u;
        #pragma unroll
        for (int w8 = 0; w8 < NWARPS; w8++) { bs += s_sum[w8]; bc += s_cnt[w8]; }
        atomicAdd(&g_sum, bs);       // merged at the L2 coherence point
        atomicAdd(&g_cnt, bc);
        unsigned int prev;           // release-only inc, self-resetting
        asm volatile("atom.release.gpu.global.inc.u32 %0, [%1], %2;"
                     : "=r"(prev)
                     : "l"(&g_done), "r"(gridDim.x - 1)
                     : "memory");
        s_is_last = (prev == gridDim.x - 1) ? 1 : 0;
    }
    __syncthreads();

    if (s_is_last && threadIdx.x == 0) {
        float        ts = atomicAdd(&g_sum, 0.0f);   // coherent L2 reads
        unsigned int tc = atomicAdd(&g_cnt, 0u);
        float nv = fmaxf((float)tc, 1.0f);
        *out = -(ts * LN2F) / nv;
        g_sum = 0.0f;   // reset for next replay (kernel boundary orders it)
        g_cnt = 0u;
    }
}

extern "C" void kernel_launch(void* const* d_in, const int* in_sizes, int n_in,
                              void* d_out, int out_size) {
    const float* input   = (const float*)d_in[0];   // [N, 21]
    const float* weight  = (const float*)d_in[1];   // [N]
    const float* pc      = (const float*)d_in[2];   // [4096]
    const int*   target  = (const int*)d_in[3];     // [N] int32
    const int*   cluster = (const int*)d_in[4];     // [N] int32
    float* out = (float*)d_out;

    int n = in_sizes[1];   // weight element count == N

    int blocks = GRID;
    int tiles = (n + TILE - 1) / TILE;
    if (tiles < blocks) blocks = tiles;   // tiny-n safety
    if (blocks < 1) blocks = 1;
    pcl_fused<<<blocks, THREADS>>>(input, weight, pc, target, cluster, n, out);
}